// round 17
// baseline (speedup 1.0000x reference)
#include <cuda_runtime.h>
#include <cuda_bf16.h>
#include <math.h>
#include <stdint.h>

#define BB     32
#define LL     4096
#define DIN    150
#define DST    75
#define HID    75
#define HIDP   80
#define TILE_L 128
#define NCHUNK (LL / TILE_L)     // 32
#define WORKS  (BB * NCHUNK)     // 1024
#define GRIDC  148
#define NTH    384               // 8 GEMM warps + 4 aux warps
#define NAUX   128
#define XKS    168               // x tile K stride in bf16 (21*16B, LDSM conflict-free)
#define XROWB  (XKS * 2)         // 336 bytes
#define XTILE_F (TILE_L * XKS / 2)   // 10752 floats per bf16 x tile
#define WKS    168
#define WROWB  (WKS * 2)
#define WFLOATS (HIDP * WKS / 2) // 6720 floats per W matrix

// smem float offsets
#define OFF_XH0 0
#define OFF_XL0 (OFF_XH0 + XTILE_F)
#define OFF_XH1 (OFF_XL0 + XTILE_F)
#define OFF_XL1 (OFF_XH1 + XTILE_F)
#define OFF_WH  (OFF_XL1 + XTILE_F)      // 43008
#define OFF_WL  (OFF_WH + WFLOATS)
#define OFF_W1  (OFF_WL + WFLOATS)
#define OFF_ES  (OFF_W1 + HIDP)          // es[2][128]
#define OFF_PS  (OFF_ES + 2 * TILE_L)
#define SMEM_FLOATS (OFF_PS + 8)         // ~227.2 KB

__device__ float g_part[BB][NCHUNK][160];
__device__ float g_psum[BB][NCHUNK];
__device__ float g_spb[BB * HIDP];       // state proj + b0 (identical per CTA)
__device__ int   g_done_b[BB];

__device__ __forceinline__ float tanh_approx(float x) {
    float t; asm("tanh.approx.f32 %0, %1;" : "=f"(t) : "f"(x)); return t;
}
__device__ __forceinline__ uint32_t smem_u32(const void* p) {
    uint32_t a;
    asm("{ .reg .u64 t; cvta.to.shared.u64 t, %1; cvt.u32.u64 %0, t; }" : "=r"(a) : "l"(p));
    return a;
}
__device__ __forceinline__ uint32_t bfpack(float2 f) {
    uint32_t r;
    asm("cvt.rn.bf16x2.f32 %0, %1, %2;" : "=r"(r) : "f"(f.y), "f"(f.x));
    return r;
}
__device__ __forceinline__ uint32_t bfres(float2 f, uint32_t h) {
    float hx = __uint_as_float(h << 16);
    float hy = __uint_as_float(h & 0xffff0000u);
    float2 r; r.x = f.x - hx; r.y = f.y - hy;
    return bfpack(r);
}
#define AUX_BAR() asm volatile("bar.sync 1, %0;" :: "n"(NAUX) : "memory")

#define LDSM_X4(r0, r1, r2, r3, addr) \
    asm volatile("ldmatrix.sync.aligned.m8n8.x4.shared.b16 {%0,%1,%2,%3}, [%4];" \
                 : "=r"(r0), "=r"(r1), "=r"(r2), "=r"(r3) : "r"(addr))

#define MMA_BF16(d, a0, a1, a2, a3, b0, b1) \
    asm volatile("mma.sync.aligned.m16n8k16.row.col.f32.bf16.bf16.f32 " \
                 "{%0,%1,%2,%3}, {%4,%5,%6,%7}, {%8,%9}, {%0,%1,%2,%3};" \
                 : "+f"((d)[0]), "+f"((d)[1]), "+f"((d)[2]), "+f"((d)[3]) \
                 : "r"(a0), "r"(a1), "r"(a2), "r"(a3), "r"(b0), "r"(b1))

// ---------------------------------------------------------------------------
// R17: aux warps pre-convert x tiles to bf16 hi/lo in LDSM-ready layout;
// GEMM warps fetch A fragments via ldmatrix (no per-tile CVT on GEMM path).
// Weighted partials computed from gmem (coalesced, L2-hot).
// ---------------------------------------------------------------------------
__global__ __launch_bounds__(NTH, 1)
void k_fused(const float* __restrict__ inputs,
             const float* __restrict__ state,
             const int*   __restrict__ cmask,
             const float* __restrict__ W0,
             const float* __restrict__ b0,
             const float* __restrict__ W1,
             const float* __restrict__ b1,
             float* __restrict__ res,
             float* __restrict__ s1_out) {
    extern __shared__ float sm[];
    float* xh[2] = { sm + OFF_XH0, sm + OFF_XH1 };
    float* xl[2] = { sm + OFF_XL0, sm + OFF_XL1 };
    float* whf   = sm + OFF_WH;
    float* wlf   = sm + OFF_WL;
    float* w1s   = sm + OFF_W1;
    float* esb   = sm + OFF_ES;       // [2][TILE_L]
    float* psred = sm + OFF_PS;
    __shared__ int s_flag;

    const int tid   = threadIdx.x;
    const int cta   = blockIdx.x;
    const int nw    = (WORKS - cta + GRIDC - 1) / GRIDC;
    const bool is_aux = (tid >= 256);
    const int a_tid = tid - 256;        // 0..127 (aux: one x-row each)
    const int lane  = tid & 31;
    const int g     = lane >> 2;
    const int tq    = lane & 3;
    const int R0    = (tid >> 5) << 4;  // GEMM warp's first row

    // --- aux: stage + convert tile 0 into buffer 0 ---
    if (is_aux) {
        int b = cta >> 5, chunk = cta & 31;
        const float2* grow = (const float2*)(inputs + ((size_t)b * LL + chunk * TILE_L + a_tid) * DIN);
        uint32_t* hrow = (uint32_t*)((char*)xh[0] + a_tid * XROWB);
        uint32_t* lrow = (uint32_t*)((char*)xl[0] + a_tid * XROWB);
#pragma unroll 5
        for (int k2 = 0; k2 < 75; ++k2) {
            float2 f = grow[k2];
            uint32_t h = bfpack(f);
            hrow[k2] = h;
            lrow[k2] = bfres(f, h);
        }
#pragma unroll
        for (int k2 = 75; k2 < 84; ++k2) { hrow[k2] = 0u; lrow[k2] = 0u; }
    }

    // --- stage W hi/lo bf16 (once): zero pads, then fill ---
    for (int idx = tid; idx < 2 * WFLOATS; idx += NTH) whf[idx] = 0.0f;
    __syncthreads();
    for (int idx = tid; idx < 150 * HIDP; idx += NTH) {
        int k = idx / HIDP, j = idx - (idx / HIDP) * HIDP;
        float v = (j < HID) ? W0[(DST + k) * HID + j] : 0.0f;
        __nv_bfloat16 h = __float2bfloat16(v);
        float l = v - __bfloat162float(h);
        ((__nv_bfloat16*)whf)[j * WKS + k] = h;
        ((__nv_bfloat16*)wlf)[j * WKS + k] = __float2bfloat16(l);
    }
    // --- state projections -> global scratch (identical values per CTA) ---
    for (int idx = tid; idx < BB * HIDP; idx += NTH) {
        int b = idx / HIDP, j = idx - (idx / HIDP) * HIDP;
        float acc = 0.0f;
        if (j < HID) {
            acc = b0[j];
            const float* st = state + b * DST;
#pragma unroll 15
            for (int k = 0; k < DST; ++k) acc = fmaf(st[k], W0[k * HID + j], acc);
        }
        g_spb[idx] = acc;
    }
    if (tid < HIDP) w1s[tid] = (tid < HID) ? W1[tid] : 0.0f;

    const float b1v = b1[0];
    const uint32_t whb4 = smem_u32(whf) + (lane & 7) * WROWB + (lane >> 3) * 16;
    const uint32_t wlb4 = whb4 + WFLOATS * 4;
    // A ldmatrix base offset (bytes within an x tile)
    const uint32_t a_off = (uint32_t)(R0 + (lane & 15)) * XROWB + ((lane >> 4) & 1) * 16;

    // ---------------- persistent work loop ----------------
    for (int wi = 0; wi < nw; ++wi) {
        const int w     = cta + wi * GRIDC;
        const int b     = w >> 5;
        const int chunk = w & 31;
        const int l0    = chunk * TILE_L;
        float* es = esb + (wi & 1) * TILE_L;

        __syncthreads();   // tile wi (hi/lo) staged; es[wi-1] visible

        if (!is_aux) {
            // ================= GEMM warps: tile wi =================
            const uint32_t ah_base = smem_u32(xh[wi & 1]) + a_off;
            const uint32_t al_base = smem_u32(xl[wi & 1]) + a_off;

            float acc[10][4];
#pragma unroll
            for (int n = 0; n < 10; ++n)
#pragma unroll
                for (int c = 0; c < 4; ++c) acc[n][c] = 0.0f;

#pragma unroll
            for (int sp = 0; sp < 5; ++sp) {
                uint32_t ahE0, ahE1, ahE2, ahE3, ahO0, ahO1, ahO2, ahO3;
                uint32_t alE0, alE1, alE2, alE3, alO0, alO1, alO2, alO3;
                LDSM_X4(ahE0, ahE1, ahE2, ahE3, ah_base + (2 * sp)     * 32);
                LDSM_X4(ahO0, ahO1, ahO2, ahO3, ah_base + (2 * sp + 1) * 32);
                LDSM_X4(alE0, alE1, alE2, alE3, al_base + (2 * sp)     * 32);
                LDSM_X4(alO0, alO1, alO2, alO3, al_base + (2 * sp + 1) * 32);

#pragma unroll
                for (int ng = 0; ng < 2; ++ng) {
                    uint32_t bh[5][4], bl[5][4];
#pragma unroll
                    for (int j = 0; j < 5; ++j) {
                        int n = ng * 5 + j;
                        LDSM_X4(bh[j][0], bh[j][1], bh[j][2], bh[j][3],
                                whb4 + n * 2688 + sp * 64);
                        LDSM_X4(bl[j][0], bl[j][1], bl[j][2], bl[j][3],
                                wlb4 + n * 2688 + sp * 64);
                    }
#pragma unroll
                    for (int j = 0; j < 5; ++j)
                        MMA_BF16(acc[ng * 5 + j], ahE0, ahE1, ahE2, ahE3, bh[j][0], bh[j][1]);
#pragma unroll
                    for (int j = 0; j < 5; ++j)
                        MMA_BF16(acc[ng * 5 + j], ahE0, ahE1, ahE2, ahE3, bl[j][0], bl[j][1]);
#pragma unroll
                    for (int j = 0; j < 5; ++j)
                        MMA_BF16(acc[ng * 5 + j], alE0, alE1, alE2, alE3, bh[j][0], bh[j][1]);
#pragma unroll
                    for (int j = 0; j < 5; ++j)
                        MMA_BF16(acc[ng * 5 + j], ahO0, ahO1, ahO2, ahO3, bh[j][2], bh[j][3]);
#pragma unroll
                    for (int j = 0; j < 5; ++j)
                        MMA_BF16(acc[ng * 5 + j], ahO0, ahO1, ahO2, ahO3, bl[j][2], bl[j][3]);
#pragma unroll
                    for (int j = 0; j < 5; ++j)
                        MMA_BF16(acc[ng * 5 + j], alO0, alO1, alO2, alO3, bh[j][2], bh[j][3]);
                }
            }

            // epilogue: tanh + dot(W1), quad reduce, mask + exp
            const float* spb = g_spb + b * HIDP;
            float sA = 0.0f, sB = 0.0f;
#pragma unroll
            for (int n = 0; n < 10; ++n) {
                int c = n * 8 + tq * 2;
                float wv0 = w1s[c], wv1 = w1s[c + 1];
                float p0 = __ldg(spb + c), p1 = __ldg(spb + c + 1);
                sA = fmaf(tanh_approx(acc[n][0] + p0), wv0, sA);
                sA = fmaf(tanh_approx(acc[n][1] + p1), wv1, sA);
                sB = fmaf(tanh_approx(acc[n][2] + p0), wv0, sB);
                sB = fmaf(tanh_approx(acc[n][3] + p1), wv1, sB);
            }
            sA += __shfl_xor_sync(0xffffffffu, sA, 1);
            sA += __shfl_xor_sync(0xffffffffu, sA, 2);
            sB += __shfl_xor_sync(0xffffffffu, sB, 1);
            sB += __shfl_xor_sync(0xffffffffu, sB, 2);
            if (tq == 0) {
                int r = R0 + g;
                size_t idx = (size_t)b * LL + l0 + r;
                float sv = sA + b1v;
                if (cmask[idx] == 0) sv -= 1e30f;
                s1_out[idx] = sv;
                es[r] = __expf(sv);
                int r2 = r + 8;
                size_t idx2 = (size_t)b * LL + l0 + r2;
                float sv2 = sB + b1v;
                if (cmask[idx2] == 0) sv2 -= 1e30f;
                s1_out[idx2] = sv2;
                es[r2] = __expf(sv2);
            }
        } else {
            // ================= aux warps =================
            if (wi > 0) {
                const int wp  = cta + (wi - 1) * GRIDC;
                const int bp  = wp >> 5;
                const int chp = wp & 31;
                const float* ep = esb + ((wi - 1) & 1) * TILE_L;
                const float* xg = inputs + ((size_t)bp * LL + chp * TILE_L) * DIN;

                // weighted partials from gmem (coalesced across aux lanes)
                for (int f = a_tid; f < DIN; f += NAUX) {
                    const float* xcol = xg + f;
                    float p0 = 0.f, p1 = 0.f, p2 = 0.f, p3 = 0.f;
#pragma unroll 4
                    for (int r = 0; r < TILE_L; r += 4) {
                        p0 = fmaf(ep[r],     __ldg(xcol + (size_t)r * DIN),       p0);
                        p1 = fmaf(ep[r + 1], __ldg(xcol + (size_t)(r + 1) * DIN), p1);
                        p2 = fmaf(ep[r + 2], __ldg(xcol + (size_t)(r + 2) * DIN), p2);
                        p3 = fmaf(ep[r + 3], __ldg(xcol + (size_t)(r + 3) * DIN), p3);
                    }
                    g_part[bp][chp][f] = (p0 + p1) + (p2 + p3);
                }
                {
                    float v = ep[a_tid];
                    v += __shfl_xor_sync(0xffffffffu, v, 16);
                    v += __shfl_xor_sync(0xffffffffu, v, 8);
                    v += __shfl_xor_sync(0xffffffffu, v, 4);
                    v += __shfl_xor_sync(0xffffffffu, v, 2);
                    v += __shfl_xor_sync(0xffffffffu, v, 1);
                    if ((a_tid & 31) == 0) psred[a_tid >> 5] = v;
                }
                AUX_BAR();
                if (a_tid == 0) {
                    g_psum[bp][chp] = (psred[0] + psred[1]) + (psred[2] + psred[3]);
                    __threadfence();
                    int old = atomicAdd(&g_done_b[bp], 1);
                    s_flag = (old == NCHUNK - 1);
                }
                AUX_BAR();
                if (s_flag) {
                    __threadfence();
                    for (int f = a_tid; f < DIN; f += NAUX) {
                        float tot = 0.0f;
#pragma unroll
                        for (int c = 0; c < NCHUNK; ++c) tot += g_psum[bp][c];
                        float p = 0.0f;
#pragma unroll
                        for (int c = 0; c < NCHUNK; ++c) p += g_part[bp][c][f];
                        res[bp * DIN + f] = p / tot;
                    }
                    if (a_tid == 0) g_done_b[bp] = 0;
                }
            }
            // stage + convert tile wi+1
            if (wi + 1 < nw) {
                int w2 = cta + (wi + 1) * GRIDC;
                int b2 = w2 >> 5, ch2 = w2 & 31;
                const float2* grow = (const float2*)(inputs + ((size_t)b2 * LL + ch2 * TILE_L + a_tid) * DIN);
                uint32_t* hrow = (uint32_t*)((char*)xh[(wi + 1) & 1] + a_tid * XROWB);
                uint32_t* lrow = (uint32_t*)((char*)xl[(wi + 1) & 1] + a_tid * XROWB);
#pragma unroll 5
                for (int k2 = 0; k2 < 75; ++k2) {
                    float2 f = grow[k2];
                    uint32_t h = bfpack(f);
                    hrow[k2] = h;
                    lrow[k2] = bfres(f, h);
                }
#pragma unroll
                for (int k2 = 75; k2 < 84; ++k2) { hrow[k2] = 0u; lrow[k2] = 0u; }
            }
        }
    }

    // ---------------- tail: partials/finish for last tile ----------------
    __syncthreads();
    if (is_aux) {
        const int wp  = cta + (nw - 1) * GRIDC;
        const int bp  = wp >> 5;
        const int chp = wp & 31;
        const float* ep = esb + ((nw - 1) & 1) * TILE_L;
        const float* xg = inputs + ((size_t)bp * LL + chp * TILE_L) * DIN;
        for (int f = a_tid; f < DIN; f += NAUX) {
            const float* xcol = xg + f;
            float p0 = 0.f, p1 = 0.f, p2 = 0.f, p3 = 0.f;
#pragma unroll 4
            for (int r = 0; r < TILE_L; r += 4) {
                p0 = fmaf(ep[r],     __ldg(xcol + (size_t)r * DIN),       p0);
                p1 = fmaf(ep[r + 1], __ldg(xcol + (size_t)(r + 1) * DIN), p1);
                p2 = fmaf(ep[r + 2], __ldg(xcol + (size_t)(r + 2) * DIN), p2);
                p3 = fmaf(ep[r + 3], __ldg(xcol + (size_t)(r + 3) * DIN), p3);
            }
            g_part[bp][chp][f] = (p0 + p1) + (p2 + p3);
        }
        {
            float v = ep[a_tid];
            v += __shfl_xor_sync(0xffffffffu, v, 16);
            v += __shfl_xor_sync(0xffffffffu, v, 8);
            v += __shfl_xor_sync(0xffffffffu, v, 4);
            v += __shfl_xor_sync(0xffffffffu, v, 2);
            v += __shfl_xor_sync(0xffffffffu, v, 1);
            if ((a_tid & 31) == 0) psred[a_tid >> 5] = v;
        }
        AUX_BAR();
        if (a_tid == 0) {
            g_psum[bp][chp] = (psred[0] + psred[1]) + (psred[2] + psred[3]);
            __threadfence();
            int old = atomicAdd(&g_done_b[bp], 1);
            s_flag = (old == NCHUNK - 1);
        }
        AUX_BAR();
        if (s_flag) {
            __threadfence();
            for (int f = a_tid; f < DIN; f += NAUX) {
                float tot = 0.0f;
#pragma unroll
                for (int c = 0; c < NCHUNK; ++c) tot += g_psum[bp][c];
                float p = 0.0f;
#pragma unroll
                for (int c = 0; c < NCHUNK; ++c) p += g_part[bp][c][f];
                res[bp * DIN + f] = p / tot;
            }
            if (a_tid == 0) g_done_b[bp] = 0;
        }
    }
}

// ---------------------------------------------------------------------------
extern "C" void kernel_launch(void* const* d_in, const int* in_sizes, int n_in,
                              void* d_out, int out_size) {
    const float* inputs = (const float*)d_in[0];
    const float* state  = (const float*)d_in[1];
    const int*   cmask  = (const int*)d_in[2];   // bool transported as int32
    const float* W0     = (const float*)d_in[3];
    const float* b0     = (const float*)d_in[4];
    const float* W1     = (const float*)d_in[5];
    const float* b1     = (const float*)d_in[6];

    float* out = (float*)d_out;
    float* res = out;                 // [B][1][DIN]
    float* s1  = out + BB * DIN;      // [B][L]

    const int smem = SMEM_FLOATS * (int)sizeof(float);
    cudaFuncSetAttribute(k_fused, cudaFuncAttributeMaxDynamicSharedMemorySize, smem);
    k_fused<<<GRIDC, NTH, smem>>>(inputs, state, cmask, W0, b0, W1, b1, res, s1);
}